// round 2
// baseline (speedup 1.0000x reference)
#include <cuda_runtime.h>

// ---------------------------------------------------------------------------
// GraphSageWithSampling — GB300 sm_103a
// Shapes (fixed by the problem): FS=128, DF=64, N=1e6,
// L = [1024000, 204800, 40960, 8192], FAN=5 (dst = repeat(arange, 5)).
// ---------------------------------------------------------------------------

#define FS 128
#define DF 64
#define L0N 1024000
#define L1N 204800
#define L2N 40960
#define L3N 8192

// Scratch hs tables (device globals: the sanctioned no-alloc scratch).
__device__ float g_hs0[(size_t)L0N * FS];   // 524 MB
__device__ float g_hs1[(size_t)L1N * FS];   // 105 MB
__device__ float g_hs2[(size_t)L2N * FS];   //  21 MB
__device__ float g_hs3[(size_t)L3N * FS];   //   4 MB

// Packed f32x2 FMA (FFMA2) — only reachable via PTX on sm_103a.
__device__ __forceinline__ unsigned long long ffma2(unsigned long long a,
                                                    unsigned long long b,
                                                    unsigned long long c) {
    unsigned long long d;
    asm("fma.rn.f32x2 %0, %1, %2, %3;" : "=l"(d) : "l"(a), "l"(b), "l"(c));
    return d;
}

__device__ __forceinline__ unsigned long long bcast2(float v) {
    float2 t = make_float2(v, v);
    return *reinterpret_cast<unsigned long long*>(&t);
}

// ---------------------------------------------------------------------------
// Kernel A: hs[n][c] = node_emb[(nid[n]+1)*128 + c]
//                      + lrelu( sum_k f[n][k] * Wp[c][k] + bp[c] )
// Block: 256 threads, 256 nodes (4 chunks of 64). Micro-tile: 8 nodes x 4 ch
// per thread, channels packed as f32x2 pairs.
// Shared: sWT[64][130] (WpT, padded), sF[64][64].
// Grid: L/256 (all L are multiples of 256).
// ---------------------------------------------------------------------------
__global__ __launch_bounds__(256) void proj_gather_kernel(
    const float* __restrict__ f, const int* __restrict__ nid,
    const float* __restrict__ node_emb, const float* __restrict__ Wp,
    const float* __restrict__ bp, float* __restrict__ hs)
{
    extern __shared__ float sm[];
    float* sWT = sm;                 // 64 * 130 = 8320 floats
    float* sF  = sm + 64 * 130;      // 64 * 64  = 4096 floats

    const int tid = threadIdx.x;
    const int tx  = tid & 31;        // lane
    const int wy  = tid >> 5;        // warp (0..7)

    // Stage Wp transposed: sWT[k*130 + c] = Wp[c*64 + k]   (coalesced reads)
    for (int idx = tid; idx < FS * DF; idx += 256) {
        int c = idx >> 6, k = idx & 63;
        sWT[k * 130 + c] = Wp[idx];
    }
    __syncthreads();

    const int base0 = blockIdx.x * 256;

    for (int ch = 0; ch < 4; ++ch) {
        const int base = base0 + ch * 64;

        // Stage f tile [64 x 64] (same linear layout as global)
        {
            const float4* fg = reinterpret_cast<const float4*>(f + (size_t)base * DF);
            float4* sF4 = reinterpret_cast<float4*>(sF);
            for (int idx = tid; idx < 64 * DF / 4; idx += 256) sF4[idx] = fg[idx];
        }
        __syncthreads();

        unsigned long long acc[8][2];
        #pragma unroll
        for (int jj = 0; jj < 8; ++jj) { acc[jj][0] = 0ull; acc[jj][1] = 0ull; }

        #pragma unroll 8
        for (int k = 0; k < DF; ++k) {
            const float* wrow = &sWT[k * 130];
            unsigned long long w0 =
                *reinterpret_cast<const unsigned long long*>(&wrow[2 * tx]);
            unsigned long long w1 =
                *reinterpret_cast<const unsigned long long*>(&wrow[2 * tx + 64]);
            #pragma unroll
            for (int jj = 0; jj < 8; ++jj) {
                unsigned long long fb = bcast2(sF[(wy + 8 * jj) * 64 + k]);
                acc[jj][0] = ffma2(w0, fb, acc[jj][0]);
                acc[jj][1] = ffma2(w1, fb, acc[jj][1]);
            }
        }

        // Epilogue: bias + leakyReLU + node_emb gather + store
        #pragma unroll
        for (int jj = 0; jj < 8; ++jj) {
            const int n = base + wy + 8 * jj;
            const int node = __ldg(&nid[n]);
            const float* emb = node_emb + (size_t)(node + 1) * FS;
            #pragma unroll
            for (int cc = 0; cc < 2; ++cc) {
                const int c0 = 2 * tx + 64 * cc;
                float2 a = *reinterpret_cast<float2*>(&acc[jj][cc]);
                a.x += __ldg(&bp[c0]);
                a.y += __ldg(&bp[c0 + 1]);
                a.x = a.x > 0.f ? a.x : 0.01f * a.x;
                a.y = a.y > 0.f ? a.y : 0.01f * a.y;
                float2 e = *reinterpret_cast<const float2*>(&emb[c0]);
                a.x += e.x;
                a.y += e.y;
                *reinterpret_cast<float2*>(&hs[(size_t)n * FS + c0]) = a;
            }
        }
        __syncthreads();   // protect sF before next chunk overwrites it
    }
}

// ---------------------------------------------------------------------------
// Kernel B: one GraphSAGE layer.
//   agg[d] = (sum_{j<5} hs_in[src[5d+j]] - hs_own[d]) / 4
//   z      = [hs_own[d] | agg[d]] @ W^T + b          (W is [128,256])
//   if lrelu: z = leaky_relu(z)
//   out[d] = z / max(||z||_2, 1e-6)
// Block: 256 threads, 64 dsts. Shared: sWT[64][130] (k-chunked), sX[64][256].
// Grid: M/64 (all M are multiples of 64). In-place out==hs_own is safe:
// each block only reads/writes its own 64 rows of hs_own.
// ---------------------------------------------------------------------------
__global__ __launch_bounds__(256) void sage_layer_kernel(
    const float* __restrict__ hs_in, const float* __restrict__ hs_own,
    const int* __restrict__ src, const float* __restrict__ W,
    const float* __restrict__ b, float* __restrict__ out, int do_lrelu)
{
    extern __shared__ float sm[];
    float* sWT = sm;                  // 64 * 130 = 8320 floats
    float* sX  = sm + 64 * 130;       // 64 * 256 = 16384 floats

    const int tid = threadIdx.x;
    const int tx  = tid & 31;
    const int wy  = tid >> 5;
    const int dBase = blockIdx.x * 64;

    // ---- Phase 1: build concat input tile sX = [h | (sum_src - h)/4] ----
    {
        const int ch4 = 4 * tx;       // each lane owns 4 channels
        #pragma unroll
        for (int j2 = 0; j2 < 8; ++j2) {
            const int dl = wy + 8 * j2;
            const int d  = dBase + dl;
            float4 h = *reinterpret_cast<const float4*>(
                hs_own + (size_t)d * FS + ch4);
            float4 s = make_float4(0.f, 0.f, 0.f, 0.f);
            const int* sp = src + (size_t)d * 5;
            #pragma unroll
            for (int j = 0; j < 5; ++j) {
                const int si = __ldg(&sp[j]);
                float4 v = *reinterpret_cast<const float4*>(
                    hs_in + (size_t)si * FS + ch4);
                s.x += v.x; s.y += v.y; s.z += v.z; s.w += v.w;
            }
            *reinterpret_cast<float4*>(&sX[dl * 256 + ch4]) = h;
            float4 agg;
            agg.x = (s.x - h.x) * 0.25f;
            agg.y = (s.y - h.y) * 0.25f;
            agg.z = (s.z - h.z) * 0.25f;
            agg.w = (s.w - h.w) * 0.25f;
            *reinterpret_cast<float4*>(&sX[dl * 256 + 128 + ch4]) = agg;
        }
    }
    __syncthreads();

    // ---- Phase 2: Z[64x128] = sX[64x256] @ W^T, k in 4 chunks of 64 ----
    unsigned long long acc[8][2];
    #pragma unroll
    for (int jj = 0; jj < 8; ++jj) { acc[jj][0] = 0ull; acc[jj][1] = 0ull; }

    for (int kc = 0; kc < 4; ++kc) {
        for (int idx = tid; idx < 64 * FS; idx += 256) {
            int c = idx >> 6, kk = idx & 63;
            sWT[kk * 130 + c] = W[(size_t)c * 256 + kc * 64 + kk];
        }
        __syncthreads();

        #pragma unroll 8
        for (int kk = 0; kk < 64; ++kk) {
            const float* wrow = &sWT[kk * 130];
            unsigned long long w0 =
                *reinterpret_cast<const unsigned long long*>(&wrow[2 * tx]);
            unsigned long long w1 =
                *reinterpret_cast<const unsigned long long*>(&wrow[2 * tx + 64]);
            const int kg = kc * 64 + kk;
            #pragma unroll
            for (int jj = 0; jj < 8; ++jj) {
                unsigned long long fb = bcast2(sX[(wy + 8 * jj) * 256 + kg]);
                acc[jj][0] = ffma2(w0, fb, acc[jj][0]);
                acc[jj][1] = ffma2(w1, fb, acc[jj][1]);
            }
        }
        __syncthreads();
    }

    // ---- Epilogue: bias, optional leakyReLU, row L2-norm, store ----
    #pragma unroll
    for (int jj = 0; jj < 8; ++jj) {
        const int d = dBase + wy + 8 * jj;
        float2 z0 = *reinterpret_cast<float2*>(&acc[jj][0]);  // ch 2tx, 2tx+1
        float2 z1 = *reinterpret_cast<float2*>(&acc[jj][1]);  // ch 64+2tx, 65+2tx
        z0.x += __ldg(&b[2 * tx]);
        z0.y += __ldg(&b[2 * tx + 1]);
        z1.x += __ldg(&b[64 + 2 * tx]);
        z1.y += __ldg(&b[65 + 2 * tx]);
        if (do_lrelu) {
            z0.x = z0.x > 0.f ? z0.x : 0.01f * z0.x;
            z0.y = z0.y > 0.f ? z0.y : 0.01f * z0.y;
            z1.x = z1.x > 0.f ? z1.x : 0.01f * z1.x;
            z1.y = z1.y > 0.f ? z1.y : 0.01f * z1.y;
        }
        float ss = z0.x * z0.x + z0.y * z0.y + z1.x * z1.x + z1.y * z1.y;
        #pragma unroll
        for (int o = 16; o; o >>= 1) ss += __shfl_xor_sync(0xffffffffu, ss, o);
        const float inv = 1.0f / fmaxf(sqrtf(ss), 1e-6f);
        z0.x *= inv; z0.y *= inv; z1.x *= inv; z1.y *= inv;
        *reinterpret_cast<float2*>(&out[(size_t)d * FS + 2 * tx]) = z0;
        *reinterpret_cast<float2*>(&out[(size_t)d * FS + 64 + 2 * tx]) = z1;
    }
}

// ---------------------------------------------------------------------------
// Launcher — 7 kernels, graph-capturable, allocation-free.
//
// Input ordering: metadata.txt follows setup_inputs() dict-insertion order,
// which INTERLEAVES f/nid and dst/src:
//   0:node_emb 1:Wp 2:bp 3:W0 4:b0 5:W1 6:b1 7:W2 8:b2
//   9:f0 10:nid0 11:f1 12:nid1 13:f2 14:nid2 15:f3 16:nid3
//   17:dst0 18:src0 19:dst1 20:src1 21:dst2 22:src2
// We disambiguate against the grouped (reference-signature) order at runtime
// via in_sizes[10]: nid0 has 1,024,000 elems (interleaved) vs f1 with
// 13,107,200 elems (grouped). dst arrays are unused (dst=repeat(arange,5)).
// ---------------------------------------------------------------------------
extern "C" void kernel_launch(void* const* d_in, const int* in_sizes, int n_in,
                              void* d_out, int out_size)
{
    const float* node_emb = (const float*)d_in[0];
    const float* Wp = (const float*)d_in[1];
    const float* bp = (const float*)d_in[2];
    const float* W0 = (const float*)d_in[3];
    const float* b0 = (const float*)d_in[4];
    const float* W1 = (const float*)d_in[5];
    const float* b1 = (const float*)d_in[6];
    const float* W2 = (const float*)d_in[7];
    const float* b2 = (const float*)d_in[8];

    const float *f0, *f1, *f2, *f3;
    const int *nid0, *nid1, *nid2, *nid3, *src0, *src1, *src2;

    if (in_sizes[10] == L0N) {
        // Interleaved (setup_inputs dict order)
        f0   = (const float*)d_in[9];
        nid0 = (const int*)  d_in[10];
        f1   = (const float*)d_in[11];
        nid1 = (const int*)  d_in[12];
        f2   = (const float*)d_in[13];
        nid2 = (const int*)  d_in[14];
        f3   = (const float*)d_in[15];
        nid3 = (const int*)  d_in[16];
        src0 = (const int*)  d_in[18];   // 17 = dst0 (unused)
        src1 = (const int*)  d_in[20];   // 19 = dst1 (unused)
        src2 = (const int*)  d_in[22];   // 21 = dst2 (unused)
    } else {
        // Grouped (reference signature order)
        f0   = (const float*)d_in[9];
        f1   = (const float*)d_in[10];
        f2   = (const float*)d_in[11];
        f3   = (const float*)d_in[12];
        nid0 = (const int*)  d_in[13];
        nid1 = (const int*)  d_in[14];
        nid2 = (const int*)  d_in[15];
        nid3 = (const int*)  d_in[16];
        src0 = (const int*)  d_in[17];
        src1 = (const int*)  d_in[18];
        src2 = (const int*)  d_in[19];
    }
    float* out = (float*)d_out;

    float *hs0, *hs1, *hs2, *hs3;
    cudaGetSymbolAddress((void**)&hs0, g_hs0);
    cudaGetSymbolAddress((void**)&hs1, g_hs1);
    cudaGetSymbolAddress((void**)&hs2, g_hs2);
    cudaGetSymbolAddress((void**)&hs3, g_hs3);

    const int SMEM_A = (64 * 130 + 64 * 64) * (int)sizeof(float);   // 49664 B
    const int SMEM_B = (64 * 130 + 64 * 256) * (int)sizeof(float);  // 98816 B
    cudaFuncSetAttribute(proj_gather_kernel,
                         cudaFuncAttributeMaxDynamicSharedMemorySize, SMEM_A);
    cudaFuncSetAttribute(sage_layer_kernel,
                         cudaFuncAttributeMaxDynamicSharedMemorySize, SMEM_B);

    // Phase A: per-layer input representations
    proj_gather_kernel<<<L0N / 256, 256, SMEM_A>>>(f0, nid0, node_emb, Wp, bp, hs0);
    proj_gather_kernel<<<L1N / 256, 256, SMEM_A>>>(f1, nid1, node_emb, Wp, bp, hs1);
    proj_gather_kernel<<<L2N / 256, 256, SMEM_A>>>(f2, nid2, node_emb, Wp, bp, hs2);
    proj_gather_kernel<<<L3N / 256, 256, SMEM_A>>>(f3, nid3, node_emb, Wp, bp, hs3);

    // Phase B: three SAGE layers (layers 0/1 in-place on hs_{i+1}; last -> out)
    sage_layer_kernel<<<L1N / 64, 256, SMEM_B>>>(hs0, hs1, src0, W0, b0, hs1, 1);
    sage_layer_kernel<<<L2N / 64, 256, SMEM_B>>>(hs1, hs2, src1, W1, b1, hs2, 1);
    sage_layer_kernel<<<L3N / 64, 256, SMEM_B>>>(hs2, hs3, src2, W2, b2, out, 0);
}